// round 1
// baseline (speedup 1.0000x reference)
#include <cuda_runtime.h>
#include <math.h>

// Problem constants (fixed by the reference)
#define B_  2048
#define T_  512
#define F_  32
#define H_  128
#define G_  512      // 4*H
#define BT  14       // batch rows per CTA -> grid = 147 = one wave on 148 SMs
#define NTHREADS 512
#define ZSTRIDE 15   // zbuf row stride (odd -> conflict-free)

// Transposed weights (k-major so per-k loads are coalesced across the 512
// gate-threads). Padded by 4 extra rows so the software-pipeline prefetch of
// the "next" k-group can read unconditionally past the end.
__device__ float g_Wih0T[(F_ + 4) * G_];
__device__ float g_Whh0T[(H_ + 4) * G_];
__device__ float g_Wih1T[(H_ + 4) * G_];
__device__ float g_Whh1T[(H_ + 4) * G_];

__global__ void transpose_all(const float* __restrict__ Wih0,
                              const float* __restrict__ Whh0,
                              const float* __restrict__ Wih1,
                              const float* __restrict__ Whh1) {
    int idx = blockIdx.x * blockDim.x + threadIdx.x;
    if (idx < G_ * F_) {
        int g = idx / F_, k = idx % F_;
        g_Wih0T[k * G_ + g] = Wih0[idx];
    }
    if (idx < G_ * H_) {
        int g = idx / H_, k = idx % H_;
        g_Whh0T[k * G_ + g] = Whh0[idx];
        g_Wih1T[k * G_ + g] = Wih1[idx];
        g_Whh1T[k * G_ + g] = Whh1[idx];
    }
}

__device__ __forceinline__ float sigm(float x) {
    return 1.0f / (1.0f + expf(-x));
}
__device__ __forceinline__ float tanh_f(float x) {
    float e = expf(-2.0f * fabsf(x));
    float t = (1.0f - e) / (1.0f + e);
    return x >= 0.0f ? t : -t;
}

// One K-panel of the gate GEMM: z[b] += sum_k h[b][k] * WT[k][g]
// WT is k-major (coalesced across g = threadIdx.x). Weights for the next
// k-group are prefetched one iteration ahead (arrays padded, so safe).
template <int KDIM>
__device__ __forceinline__ void gemm_panel(const float* __restrict__ WT,
                                           const float4* __restrict__ hv,
                                           float* z, int g) {
    constexpr int KG = KDIM / 4;
    float w0 = WT[0 * G_ + g];
    float w1 = WT[1 * G_ + g];
    float w2 = WT[2 * G_ + g];
    float w3 = WT[3 * G_ + g];
#pragma unroll 1
    for (int kg = 0; kg < KG; ++kg) {
        const float* nw = WT + (size_t)((kg + 1) * 4) * G_ + g;
        float n0 = nw[0];
        float n1 = nw[G_];
        float n2 = nw[2 * G_];
        float n3 = nw[3 * G_];
#pragma unroll
        for (int b = 0; b < BT; ++b) {
            float4 v = hv[b * KG + kg];
            float zb = z[b];
            zb = fmaf(v.x, w0, zb);
            zb = fmaf(v.y, w1, zb);
            zb = fmaf(v.z, w2, zb);
            zb = fmaf(v.w, w3, zb);
            z[b] = zb;
        }
        w0 = n0; w1 = n1; w2 = n2; w3 = n3;
    }
}

extern __shared__ float smem[];

__global__ void __launch_bounds__(NTHREADS, 1)
lstm_persistent(const float* __restrict__ x,
                const float* __restrict__ b0,
                const float* __restrict__ b1,
                const float* __restrict__ Wfc,
                const float* __restrict__ bfc,
                float* __restrict__ out) {
    // SMEM layout
    float* h0 = smem;                    // BT*H_
    float* c0 = h0 + BT * H_;            // BT*H_
    float* h1 = c0 + BT * H_;            // BT*H_
    float* c1 = h1 + BT * H_;            // BT*H_
    float* zbuf = c1 + BT * H_;          // G_ * ZSTRIDE
    float* xs = zbuf + G_ * ZSTRIDE;     // BT*F_

    const int tid = threadIdx.x;
    const int g = tid;                   // gate index 0..511 (phase A)
    const int b_base = blockIdx.x * BT;
    const int nb = min(BT, B_ - b_base);

    // zero h/c (contiguous block at smem start)
    for (int i = tid; i < 4 * BT * H_; i += NTHREADS) smem[i] = 0.0f;

    const float bias0 = b0[g];
    const float bias1 = b1[g];
    __syncthreads();

    const float4* h0v = (const float4*)h0;
    const float4* h1v = (const float4*)h1;
    const float4* xsv = (const float4*)xs;

    for (int t = 0; t < T_; ++t) {
        // stage x_t for this batch tile
        for (int i = tid; i < BT * F_; i += NTHREADS) {
            int b = i / F_, f = i % F_;
            xs[i] = (b < nb)
                ? x[((size_t)(b_base + b) * T_ + t) * F_ + f]
                : 0.0f;
        }
        __syncthreads();

        // ---------- layer 0: z = b0 + x_t@Wih0^T + h0@Whh0^T ----------
        float z[BT];
#pragma unroll
        for (int b = 0; b < BT; ++b) z[b] = bias0;
        gemm_panel<F_>(g_Wih0T, xsv, z, g);
        gemm_panel<H_>(g_Whh0T, h0v, z, g);
#pragma unroll
        for (int b = 0; b < BT; ++b) zbuf[g * ZSTRIDE + b] = z[b];
        __syncthreads();

        // gate update layer 0
        for (int i = tid; i < BT * H_; i += NTHREADS) {
            int b = i >> 7, j = i & (H_ - 1);
            float zi = zbuf[(j      ) * ZSTRIDE + b];
            float zf = zbuf[(j + 128) * ZSTRIDE + b];
            float zg = zbuf[(j + 256) * ZSTRIDE + b];
            float zo = zbuf[(j + 384) * ZSTRIDE + b];
            float ii = sigm(zi);
            float ff = sigm(zf);
            float gg = tanh_f(zg);
            float oo = sigm(zo);
            float c = ff * c0[i] + ii * gg;
            c0[i] = c;
            h0[i] = oo * tanh_f(c);
        }
        __syncthreads();

        // ---------- layer 1: z = b1 + h0_t@Wih1^T + h1@Whh1^T ----------
#pragma unroll
        for (int b = 0; b < BT; ++b) z[b] = bias1;
        gemm_panel<H_>(g_Wih1T, h0v, z, g);
        gemm_panel<H_>(g_Whh1T, h1v, z, g);
#pragma unroll
        for (int b = 0; b < BT; ++b) zbuf[g * ZSTRIDE + b] = z[b];
        __syncthreads();

        // gate update layer 1
        for (int i = tid; i < BT * H_; i += NTHREADS) {
            int b = i >> 7, j = i & (H_ - 1);
            float zi = zbuf[(j      ) * ZSTRIDE + b];
            float zf = zbuf[(j + 128) * ZSTRIDE + b];
            float zg = zbuf[(j + 256) * ZSTRIDE + b];
            float zo = zbuf[(j + 384) * ZSTRIDE + b];
            float ii = sigm(zi);
            float ff = sigm(zf);
            float gg = tanh_f(zg);
            float oo = sigm(zo);
            float c = ff * c1[i] + ii * gg;
            c1[i] = c;
            h1[i] = oo * tanh_f(c);
        }
        __syncthreads();
    }

    // FC head: out[b] = h1_last[b] . Wfc + bfc
    if (tid < nb) {
        float s = bfc[0];
#pragma unroll
        for (int k = 0; k < H_; ++k) s = fmaf(h1[tid * H_ + k], Wfc[k], s);
        out[b_base + tid] = s;
    }
}

extern "C" void kernel_launch(void* const* d_in, const int* in_sizes, int n_in,
                              void* d_out, int out_size) {
    const float* x    = (const float*)d_in[0];
    const float* Wih0 = (const float*)d_in[1];
    const float* Whh0 = (const float*)d_in[2];
    const float* b0   = (const float*)d_in[3];
    const float* Wih1 = (const float*)d_in[4];
    const float* Whh1 = (const float*)d_in[5];
    const float* b1   = (const float*)d_in[6];
    const float* Wfc  = (const float*)d_in[7];
    const float* bfc  = (const float*)d_in[8];
    float* out = (float*)d_out;

    (void)in_sizes; (void)n_in; (void)out_size;

    // one-time (per launch) weight transpose into k-major device scratch
    transpose_all<<<(G_ * H_ + 255) / 256, 256>>>(Wih0, Whh0, Wih1, Whh1);

    const int smem_bytes = (4 * BT * H_ + G_ * ZSTRIDE + BT * F_) * sizeof(float);
    cudaFuncSetAttribute(lstm_persistent,
                         cudaFuncAttributeMaxDynamicSharedMemorySize,
                         smem_bytes);

    lstm_persistent<<<(B_ + BT - 1) / BT, NTHREADS, smem_bytes>>>(
        x, b0, b1, Wfc, bfc, out);
}

// round 2
// speedup vs baseline: 1.1331x; 1.1331x over previous
#include <cuda_runtime.h>
#include <math.h>

// Problem constants
#define B_  2048
#define T_  512
#define F_  32
#define H_  128
#define G_  512      // 4*H
#define BT  14       // batch rows per CTA -> 147 CTAs = one wave on 148 SMs
#define P_  7        // batch-row pairs per CTA
#define NT  256      // threads; each owns gates tid and tid+256
#define PST 9        // zbuf pair stride (18 words -> only 2-way bank conflict)

typedef unsigned long long ull;

// k-major transposed weights, each scalar DUPLICATED as {w,w} so it loads as a
// ready-made 64-bit packed operand for fma.rn.f32x2. Padded +4 k-rows so the
// one-ahead prefetch can read unconditionally.
__device__ float2 g_Wih0T[(F_ + 4) * G_];
__device__ float2 g_Whh0T[(H_ + 4) * G_];
__device__ float2 g_Wih1T[(H_ + 4) * G_];
__device__ float2 g_Whh1T[(H_ + 4) * G_];

__global__ void transpose_all(const float* __restrict__ Wih0,
                              const float* __restrict__ Whh0,
                              const float* __restrict__ Wih1,
                              const float* __restrict__ Whh1) {
    int idx = blockIdx.x * blockDim.x + threadIdx.x;
    if (idx < G_ * F_) {
        int g = idx / F_, k = idx % F_;
        float w = Wih0[idx];
        g_Wih0T[k * G_ + g] = make_float2(w, w);
    }
    if (idx < G_ * H_) {
        int g = idx / H_, k = idx % H_;
        float w;
        w = Whh0[idx]; g_Whh0T[k * G_ + g] = make_float2(w, w);
        w = Wih1[idx]; g_Wih1T[k * G_ + g] = make_float2(w, w);
        w = Whh1[idx]; g_Whh1T[k * G_ + g] = make_float2(w, w);
    }
}

__device__ __forceinline__ ull ffma2(ull a, ull b, ull c) {
    ull d;
    asm("fma.rn.f32x2 %0, %1, %2, %3;" : "=l"(d) : "l"(a), "l"(b), "l"(c));
    return d;
}

__device__ __forceinline__ ull pack2(float lo, float hi) {
    return (ull)__float_as_uint(lo) | ((ull)__float_as_uint(hi) << 32);
}

__device__ __forceinline__ float sigm(float x) {
    return 1.0f / (1.0f + __expf(-x));
}
__device__ __forceinline__ float tanh_f(float x) {
    float e = __expf(-2.0f * fabsf(x));
    float t = (1.0f - e) / (1.0f + e);
    return x >= 0.0f ? t : -t;
}

// One K-panel: z[gate][p] += sum_k hpair[p][k] * W[k][g], all in f32x2 pairs.
// hp: pair-packed activations, P_ rows of KDIM float2 (16B-aligned).
// WT: duplicated k-major weights. Next k-group prefetched one iter ahead.
template <int KDIM>
__device__ __forceinline__ void gemm2(const float2* __restrict__ WT,
                                      const float2* __restrict__ hp,
                                      ull z[2][P_], int g0) {
    constexpr int KG = KDIM / 4;
    const ull* W0 = (const ull*)WT + g0;
    const ull* W1 = (const ull*)WT + g0 + 256;
    ull w[2][4];
#pragma unroll
    for (int q = 0; q < 4; ++q) { w[0][q] = W0[q * G_]; w[1][q] = W1[q * G_]; }
#pragma unroll 1
    for (int kg = 0; kg < KG; ++kg) {
        const ull* nW0 = W0 + (size_t)(kg + 1) * 4 * G_;
        const ull* nW1 = W1 + (size_t)(kg + 1) * 4 * G_;
        ull nw[2][4];
#pragma unroll
        for (int q = 0; q < 4; ++q) { nw[0][q] = nW0[q * G_]; nw[1][q] = nW1[q * G_]; }
#pragma unroll
        for (int p = 0; p < P_; ++p) {
            const ulonglong2* hv = (const ulonglong2*)(hp + p * KDIM);
            ulonglong2 v0 = hv[2 * kg];      // pairs for k=4kg, 4kg+1
            ulonglong2 v1 = hv[2 * kg + 1];  // pairs for k=4kg+2, 4kg+3
            ull z0 = z[0][p], z1 = z[1][p];
            z0 = ffma2(v0.x, w[0][0], z0);
            z0 = ffma2(v0.y, w[0][1], z0);
            z0 = ffma2(v1.x, w[0][2], z0);
            z0 = ffma2(v1.y, w[0][3], z0);
            z1 = ffma2(v0.x, w[1][0], z1);
            z1 = ffma2(v0.y, w[1][1], z1);
            z1 = ffma2(v1.x, w[1][2], z1);
            z1 = ffma2(v1.y, w[1][3], z1);
            z[0][p] = z0; z[1][p] = z1;
        }
#pragma unroll
        for (int q = 0; q < 4; ++q) { w[0][q] = nw[0][q]; w[1][q] = nw[1][q]; }
    }
}

extern __shared__ float2 smem2[];

__global__ void __launch_bounds__(NT, 1)
lstm_persistent(const float* __restrict__ x,
                const float* __restrict__ b0,
                const float* __restrict__ b1,
                const float* __restrict__ Wfc,
                const float* __restrict__ bfc,
                float* __restrict__ out) {
    // SMEM layout (float2 units); every array 16B-aligned
    float2* h0p = smem2;                 // P_*H_
    float2* c0p = h0p + P_ * H_;         // P_*H_
    float2* h1p = c0p + P_ * H_;         // P_*H_
    float2* c1p = h1p + P_ * H_;         // P_*H_
    float2* zb  = c1p + P_ * H_;         // G_*PST
    float2* xp  = zb + G_ * PST;         // P_*F_
    ull* zbu = (ull*)zb;

    const int tid = threadIdx.x;
    const int g0 = tid;                  // this thread's gates: g0, g0+256
    const int b_base = blockIdx.x * BT;
    const int nb = min(BT, B_ - b_base);

    for (int i = tid; i < 4 * P_ * H_; i += NT)
        smem2[i] = make_float2(0.0f, 0.0f);

    const ull bias0a = pack2(b0[g0], b0[g0]);
    const ull bias0b = pack2(b0[g0 + 256], b0[g0 + 256]);
    const ull bias1a = pack2(b1[g0], b1[g0]);
    const ull bias1b = pack2(b1[g0 + 256], b1[g0 + 256]);
    __syncthreads();

    for (int t = 0; t < T_; ++t) {
        // stage x_t, pair-interleaved: xp[p*F + f] = {x[2p][f], x[2p+1][f]}
        for (int i = tid; i < BT * F_; i += NT) {
            int b = i / F_, f = i % F_;
            float v = (b < nb)
                ? x[((size_t)(b_base + b) * T_ + t) * F_ + f]
                : 0.0f;
            ((float*)xp)[(b >> 1) * F_ * 2 + f * 2 + (b & 1)] = v;
        }
        __syncthreads();

        // ---------- layer 0 ----------
        ull z[2][P_];
#pragma unroll
        for (int p = 0; p < P_; ++p) { z[0][p] = bias0a; z[1][p] = bias0b; }
        gemm2<F_>(g_Wih0T, xp, z, g0);
        gemm2<H_>(g_Whh0T, h0p, z, g0);
#pragma unroll
        for (int p = 0; p < P_; ++p) {
            zbu[g0 * PST + p] = z[0][p];
            zbu[(g0 + 256) * PST + p] = z[1][p];
        }
        __syncthreads();

        for (int i = tid; i < P_ * H_; i += NT) {
            int p = i >> 7, j = i & (H_ - 1);
            float2 zi = zb[(j      ) * PST + p];
            float2 zf = zb[(j + 128) * PST + p];
            float2 zg = zb[(j + 256) * PST + p];
            float2 zo = zb[(j + 384) * PST + p];
            float2 c = c0p[p * H_ + j];
            float2 nc, nh;
            nc.x = sigm(zf.x) * c.x + sigm(zi.x) * tanh_f(zg.x);
            nc.y = sigm(zf.y) * c.y + sigm(zi.y) * tanh_f(zg.y);
            nh.x = sigm(zo.x) * tanh_f(nc.x);
            nh.y = sigm(zo.y) * tanh_f(nc.y);
            c0p[p * H_ + j] = nc;
            h0p[p * H_ + j] = nh;
        }
        __syncthreads();

        // ---------- layer 1 ----------
#pragma unroll
        for (int p = 0; p < P_; ++p) { z[0][p] = bias1a; z[1][p] = bias1b; }
        gemm2<H_>(g_Wih1T, h0p, z, g0);
        gemm2<H_>(g_Whh1T, h1p, z, g0);
#pragma unroll
        for (int p = 0; p < P_; ++p) {
            zbu[g0 * PST + p] = z[0][p];
            zbu[(g0 + 256) * PST + p] = z[1][p];
        }
        __syncthreads();

        for (int i = tid; i < P_ * H_; i += NT) {
            int p = i >> 7, j = i & (H_ - 1);
            float2 zi = zb[(j      ) * PST + p];
            float2 zf = zb[(j + 128) * PST + p];
            float2 zg = zb[(j + 256) * PST + p];
            float2 zo = zb[(j + 384) * PST + p];
            float2 c = c1p[p * H_ + j];
            float2 nc, nh;
            nc.x = sigm(zf.x) * c.x + sigm(zi.x) * tanh_f(zg.x);
            nc.y = sigm(zf.y) * c.y + sigm(zi.y) * tanh_f(zg.y);
            nh.x = sigm(zo.x) * tanh_f(nc.x);
            nh.y = sigm(zo.y) * tanh_f(nc.y);
            c1p[p * H_ + j] = nc;
            h1p[p * H_ + j] = nh;
        }
        __syncthreads();
    }

    // FC head: out[b] = h1_last[b] . Wfc + bfc
    if (tid < nb) {
        float s = bfc[0];
#pragma unroll
        for (int k = 0; k < H_; ++k) {
            float2 hv = h1p[(tid >> 1) * H_ + k];
            float h = (tid & 1) ? hv.y : hv.x;
            s = fmaf(h, Wfc[k], s);
        }
        out[b_base + tid] = s;
    }
}

extern "C" void kernel_launch(void* const* d_in, const int* in_sizes, int n_in,
                              void* d_out, int out_size) {
    const float* x    = (const float*)d_in[0];
    const float* Wih0 = (const float*)d_in[1];
    const float* Whh0 = (const float*)d_in[2];
    const float* b0   = (const float*)d_in[3];
    const float* Wih1 = (const float*)d_in[4];
    const float* Whh1 = (const float*)d_in[5];
    const float* b1   = (const float*)d_in[6];
    const float* Wfc  = (const float*)d_in[7];
    const float* bfc  = (const float*)d_in[8];
    float* out = (float*)d_out;
    (void)in_sizes; (void)n_in; (void)out_size;

    transpose_all<<<(G_ * H_ + 255) / 256, 256>>>(Wih0, Whh0, Wih1, Whh1);

    const int smem_bytes = (4 * P_ * H_ + G_ * PST + P_ * F_) * sizeof(float2);
    cudaFuncSetAttribute(lstm_persistent,
                         cudaFuncAttributeMaxDynamicSharedMemorySize,
                         smem_bytes);

    lstm_persistent<<<(B_ + BT - 1) / BT, NT, smem_bytes>>>(
        x, b0, b1, Wfc, bfc, out);
}